// round 14
// baseline (speedup 1.0000x reference)
#include <cuda_runtime.h>
#include <cuda_bf16.h>
#include <cstdint>

#define S_LEN 1024
#define BDIM  2
#define HQ    4096
#define NKV   8
#define NH    64
#define DH    64
#define MROWS (BDIM * S_LEN)   // 2048
#define KVDIM (NKV * DH)       // 512

// ---------------- scratch (device globals; no allocs allowed) ----------------
__device__ float g_q [MROWS * HQ];
__device__ float g_k [MROWS * KVDIM];
__device__ float g_v [MROWS * KVDIM];
__device__ __nv_bfloat16 g_hsH[MROWS * HQ], g_hsL[MROWS * HQ];
__device__ __nv_bfloat16 g_aoH[MROWS * HQ], g_aoL[MROWS * HQ];
__device__ __nv_bfloat16 g_qsH[MROWS * HQ], g_qsL[MROWS * HQ];
__device__ __nv_bfloat16 g_ksH[MROWS * KVDIM], g_ksL[MROWS * KVDIM];
__device__ __nv_bfloat16 g_vtH[MROWS * KVDIM], g_vtL[MROWS * KVDIM];
__device__ __nv_bfloat16 g_wqH[HQ * HQ],    g_wqL[HQ * HQ];
__device__ __nv_bfloat16 g_wdH[HQ * HQ],    g_wdL[HQ * HQ];
__device__ __nv_bfloat16 g_wkH[KVDIM * HQ], g_wkL[KVDIM * HQ];
__device__ __nv_bfloat16 g_wvH[KVDIM * HQ], g_wvL[KVDIM * HQ];

// ---------------- helpers ----------------
__device__ __forceinline__ void split2(float x, float y, uint32_t& hi, uint32_t& lo)
{
    __nv_bfloat16 hx = __float2bfloat16(x), hy = __float2bfloat16(y);
    __nv_bfloat16 lx = __float2bfloat16(x - __bfloat162float(hx));
    __nv_bfloat16 ly = __float2bfloat16(y - __bfloat162float(hy));
    __nv_bfloat162 H = __halves2bfloat162(hx, hy);
    __nv_bfloat162 L = __halves2bfloat162(lx, ly);
    hi = *(uint32_t*)&H; lo = *(uint32_t*)&L;
}

#define MMA_BF16(d, av, b0, b1) \
    asm volatile("mma.sync.aligned.m16n8k16.row.col.f32.bf16.bf16.f32 " \
                 "{%0,%1,%2,%3}, {%4,%5,%6,%7}, {%8,%9}, {%0,%1,%2,%3};\n" \
                 : "+f"(d[0]), "+f"(d[1]), "+f"(d[2]), "+f"(d[3]) \
                 : "r"(av[0]), "r"(av[1]), "r"(av[2]), "r"(av[3]), \
                   "r"(b0), "r"(b1))

#define LDSM4(d0, d1, d2, d3, a) \
    asm volatile("ldmatrix.sync.aligned.m8n8.x4.shared.b16 {%0,%1,%2,%3}, [%4];\n" \
                 : "=r"(d0), "=r"(d1), "=r"(d2), "=r"(d3) : "r"(a))

__device__ __forceinline__ void cp16(uint32_t sa, const void* g)
{
    asm volatile("cp.async.cg.shared.global [%0], [%1], 16;\n" :: "r"(sa), "l"(g));
}
#define CP_COMMIT() asm volatile("cp.async.commit_group;\n" ::: "memory")
#define CP_WAIT1()  asm volatile("cp.async.wait_group 1;\n" ::: "memory")

// ---------------- fp32 -> (hi, lo) bf16 split ----------------
__global__ void __launch_bounds__(256) split_kernel(
    const float* __restrict__ x, __nv_bfloat16* __restrict__ hi,
    __nv_bfloat16* __restrict__ lo, int n4)
{
    int i = blockIdx.x * blockDim.x + threadIdx.x;
    if (i >= n4) return;
    float4 v = ((const float4*)x)[i];
    uint32_t h0, l0, h1, l1;
    split2(v.x, v.y, h0, l0);
    split2(v.z, v.w, h1, l1);
    uint32_t* hp = (uint32_t*)hi + (size_t)i * 2;
    uint32_t* lp = (uint32_t*)lo + (size_t)i * 2;
    hp[0] = h0; hp[1] = h1;
    lp[0] = l0; lp[1] = l1;
}

// ---------------- bf16 split-GEMM, cp.async double-buffered, ldmatrix ----------------
// C[m,n] = sum_k A[m,k]*W[n,k];  C = Ah*Bh + Al*Bh + Ah*Bl  (fp32 accum)
#define GBM 128
#define GBN 128
#define GBK 32
#define ASTR 40
#define GTILE (GBM * ASTR)            // elements per array per stage
#define GEMM_SMEM (2 * 4 * GTILE * 2) // bytes

__device__ __forceinline__ void gemm3_body(
    const __nv_bfloat16* __restrict__ AH, const __nv_bfloat16* __restrict__ AL,
    const __nv_bfloat16* __restrict__ BH, const __nv_bfloat16* __restrict__ BL,
    float* __restrict__ C, int K, int N, int m0, int n0, __nv_bfloat16* smem)
{
    const int tid  = threadIdx.x;
    const int wid  = tid >> 5;
    const int lane = tid & 31;
    const int wm = (wid & 1) * 64;
    const int wn = (wid >> 1) * 32;
    const int fr = lane >> 2;
    const int fc = (lane & 3) * 2;

    float acc[4][4][4];
#pragma unroll
    for (int mt = 0; mt < 4; mt++)
#pragma unroll
        for (int nt = 0; nt < 4; nt++)
#pragma unroll
            for (int e = 0; e < 4; e++) acc[mt][nt][e] = 0.f;

    int offA[4], offB[2];
#pragma unroll
    for (int mt = 0; mt < 4; mt++)
        offA[mt] = ((wm + mt * 16 + (lane & 7) + ((lane >> 3) & 1) * 8) * ASTR
                    + (lane >> 4) * 8) * 2;
#pragma unroll
    for (int p = 0; p < 2; p++)
        offB[p] = ((wn + p * 16 + (lane >> 4) * 8 + (lane & 7)) * ASTR
                   + ((lane >> 3) & 1) * 8) * 2;

    const uint32_t su = (uint32_t)__cvta_generic_to_shared(smem);

    auto load_stage = [&](int s, int k0) {
        __nv_bfloat16* base = smem + s * 4 * GTILE;
#pragma unroll
        for (int r = 0; r < 2; r++) {
            int slot = tid + 256 * r;
            int row  = slot >> 2;
            int q    = (slot & 3) * 8;
            size_t ga = (size_t)(m0 + row) * K + k0 + q;
            size_t gb = (size_t)(n0 + row) * K + k0 + q;
            uint32_t da = (uint32_t)__cvta_generic_to_shared(base + row * ASTR + q);
            cp16(da,             AH + ga);
            cp16(da + 2*GTILE,   AL + ga);
            cp16(da + 4*GTILE,   BH + gb);
            cp16(da + 6*GTILE,   BL + gb);
        }
    };

    load_stage(0, 0);
    CP_COMMIT();

    int s = 0;
    for (int k0 = 0; k0 < K; k0 += GBK) {
        if (k0 + GBK < K) load_stage(s ^ 1, k0 + GBK);
        CP_COMMIT();
        CP_WAIT1();
        __syncthreads();

        uint32_t sb  = su + s * (4 * GTILE * 2);
        uint32_t aAH = sb,              aAL = sb + 2 * GTILE;
        uint32_t aBH = sb + 4 * GTILE,  aBL = sb + 6 * GTILE;

#pragma unroll
        for (int kk = 0; kk < GBK; kk += 16) {
            uint32_t bh[4][2], bl[4][2];
            LDSM4(bh[0][0], bh[0][1], bh[1][0], bh[1][1], aBH + offB[0] + kk * 2);
            LDSM4(bh[2][0], bh[2][1], bh[3][0], bh[3][1], aBH + offB[1] + kk * 2);
            LDSM4(bl[0][0], bl[0][1], bl[1][0], bl[1][1], aBL + offB[0] + kk * 2);
            LDSM4(bl[2][0], bl[2][1], bl[3][0], bl[3][1], aBL + offB[1] + kk * 2);
            uint32_t a[4][4];
#pragma unroll
            for (int mt = 0; mt < 4; mt++)
                LDSM4(a[mt][0], a[mt][1], a[mt][2], a[mt][3], aAH + offA[mt] + kk * 2);
#pragma unroll
            for (int mt = 0; mt < 4; mt++)
#pragma unroll
                for (int nt = 0; nt < 4; nt++) {
                    MMA_BF16(acc[mt][nt], a[mt], bh[nt][0], bh[nt][1]);
                    MMA_BF16(acc[mt][nt], a[mt], bl[nt][0], bl[nt][1]);
                }
#pragma unroll
            for (int mt = 0; mt < 4; mt++)
                LDSM4(a[mt][0], a[mt][1], a[mt][2], a[mt][3], aAL + offA[mt] + kk * 2);
#pragma unroll
            for (int mt = 0; mt < 4; mt++)
#pragma unroll
                for (int nt = 0; nt < 4; nt++)
                    MMA_BF16(acc[mt][nt], a[mt], bh[nt][0], bh[nt][1]);
        }
        __syncthreads();
        s ^= 1;
    }

#pragma unroll
    for (int mt = 0; mt < 4; mt++)
#pragma unroll
        for (int nt = 0; nt < 4; nt++) {
            size_t base = (size_t)(m0 + wm + mt * 16 + fr) * N + n0 + wn + nt * 8 + fc;
            *(float2*)&C[base]                 = make_float2(acc[mt][nt][0], acc[mt][nt][1]);
            *(float2*)&C[base + 8 * (size_t)N] = make_float2(acc[mt][nt][2], acc[mt][nt][3]);
        }
}

__global__ void __launch_bounds__(256, 2) gemm3_kernel(
    const __nv_bfloat16* __restrict__ AH, const __nv_bfloat16* __restrict__ AL,
    const __nv_bfloat16* __restrict__ BH, const __nv_bfloat16* __restrict__ BL,
    float* __restrict__ C, int K, int N)
{
    extern __shared__ __nv_bfloat16 smem[];
    gemm3_body(AH, AL, BH, BL, C, K, N, blockIdx.y * GBM, blockIdx.x * GBN, smem);
}

// fused K+V projection: grid.x = 8; 0..3 -> K, 4..7 -> V
__global__ void __launch_bounds__(256, 2) gemm3_kv_kernel(
    const __nv_bfloat16* __restrict__ AH, const __nv_bfloat16* __restrict__ AL,
    const __nv_bfloat16* __restrict__ KH, const __nv_bfloat16* __restrict__ KL,
    const __nv_bfloat16* __restrict__ VH, const __nv_bfloat16* __restrict__ VL,
    float* __restrict__ Ck, float* __restrict__ Cv)
{
    extern __shared__ __nv_bfloat16 smem[];
    const __nv_bfloat16 *BH, *BL;
    float* C;
    int n0;
    if (blockIdx.x < 4) { BH = KH; BL = KL; C = Ck; n0 = blockIdx.x * GBN; }
    else                { BH = VH; BL = VL; C = Cv; n0 = (blockIdx.x - 4) * GBN; }
    gemm3_body(AH, AL, BH, BL, C, HQ, KVDIM, blockIdx.y * GBM, n0, smem);
}

// ---------------- RoPE + hi/lo split ----------------
__global__ void rope_split_kernel(
    const float* __restrict__ p, const float* __restrict__ cosb,
    const float* __restrict__ sinb, __nv_bfloat16* __restrict__ outH,
    __nv_bfloat16* __restrict__ outL, int nheads, float scl)
{
    int idx = blockIdx.x * blockDim.x + threadIdx.x;
    int total = MROWS * nheads * (DH / 2);
    if (idx >= total) return;
    int d  = idx & 31;
    int h  = (idx >> 5) % nheads;
    int bs = idx / (nheads * 32);
    int s  = bs & (S_LEN - 1);
    size_t base = (size_t)bs * nheads * DH + h * DH;
    float x1 = p[base + d];
    float x2 = p[base + d + 32];
    float c1 = cosb[s * DH + d],      s1 = sinb[s * DH + d];
    float c2 = cosb[s * DH + d + 32], s2 = sinb[s * DH + d + 32];
    float y1 = (x1 * c1 - x2 * s1) * scl;
    float y2 = (x2 * c2 + x1 * s2) * scl;
    __nv_bfloat16 h1 = __float2bfloat16(y1);
    __nv_bfloat16 h2 = __float2bfloat16(y2);
    outH[base + d]      = h1;
    outH[base + d + 32] = h2;
    outL[base + d]      = __float2bfloat16(y1 - __bfloat162float(h1));
    outL[base + d + 32] = __float2bfloat16(y2 - __bfloat162float(h2));
}

// ---------------- V split + transpose ----------------
__global__ void __launch_bounds__(256) splitvt_kernel(
    const float* __restrict__ v, __nv_bfloat16* __restrict__ vtH,
    __nv_bfloat16* __restrict__ vtL)
{
    __shared__ float sm[64][65];
    const int s0  = blockIdx.x * 64;
    const int kvh = blockIdx.y;
    const int b   = blockIdx.z;
    const int tid = threadIdx.x;

#pragma unroll
    for (int r = 0; r < 16; r++) {
        int slot = tid + 256 * r;
        int sl = slot >> 6;
        int d  = slot & 63;
        sm[d][sl] = v[(size_t)(b * S_LEN + s0 + sl) * KVDIM + kvh * DH + d];
    }
    __syncthreads();
#pragma unroll
    for (int r = 0; r < 16; r++) {
        int slot = tid + 256 * r;
        int d  = slot >> 6;
        int sl = slot & 63;
        float x = sm[d][sl];
        __nv_bfloat16 h = __float2bfloat16(x);
        size_t o = ((size_t)((b * NKV + kvh) * DH + d)) * S_LEN + s0 + sl;
        vtH[o] = h;
        vtL[o] = __float2bfloat16(x - __bfloat162float(h));
    }
}

// ---------------- Flash attention: tensor cores + cp.async pipeline + ldmatrix ----------------
// One batch per launch (pointers pre-offset); LPT heavy-first tile order.
#define ATS 72
#define ATILE (64 * ATS)               // elements per array per stage
#define ATT_SMEM (2 * 4 * ATILE * 2)   // bytes

__global__ void __launch_bounds__(128) attn_mma_kernel(
    const __nv_bfloat16* __restrict__ qH, const __nv_bfloat16* __restrict__ qL,
    const __nv_bfloat16* __restrict__ kH, const __nv_bfloat16* __restrict__ kL,
    const __nv_bfloat16* __restrict__ vH, const __nv_bfloat16* __restrict__ vL,
    __nv_bfloat16* __restrict__ oH, __nv_bfloat16* __restrict__ oL)
{
    extern __shared__ __nv_bfloat16 smem[];

    const int h   = blockIdx.y;
    const int kvh = h >> 3;
    // heavy-first (LPT): largest causal extent launches earliest
    const int q0  = (gridDim.x - 1 - blockIdx.x) * 64;
    const int tid  = threadIdx.x;
    const int w    = tid >> 5;
    const int lane = tid & 31;
    const int fr = lane >> 2;
    const int fc = (lane & 3) * 2;
    const int qrow = q0 + w * 16;

    int offK[4];
#pragma unroll
    for (int p = 0; p < 4; p++)
        offK[p] = ((p * 16 + (lane >> 4) * 8 + (lane & 7)) * ATS
                   + ((lane >> 3) & 1) * 8) * 2;

    const uint32_t su = (uint32_t)__cvta_generic_to_shared(smem);

    uint32_t aH[4][4], aL[4][4];
    {
        const __nv_bfloat16* p0 = qH + (size_t)(qrow + fr) * HQ + h * DH + fc;
        const __nv_bfloat16* p1 = qL + (size_t)(qrow + fr) * HQ + h * DH + fc;
#pragma unroll
        for (int kc = 0; kc < 4; kc++) {
            aH[kc][0] = *(const uint32_t*)(p0 + kc * 16);
            aH[kc][1] = *(const uint32_t*)(p0 + kc * 16 + 8 * HQ);
            aH[kc][2] = *(const uint32_t*)(p0 + kc * 16 + 8);
            aH[kc][3] = *(const uint32_t*)(p0 + kc * 16 + 8 * HQ + 8);
            aL[kc][0] = *(const uint32_t*)(p1 + kc * 16);
            aL[kc][1] = *(const uint32_t*)(p1 + kc * 16 + 8 * HQ);
            aL[kc][2] = *(const uint32_t*)(p1 + kc * 16 + 8);
            aL[kc][3] = *(const uint32_t*)(p1 + kc * 16 + 8 * HQ + 8);
        }
    }

    float oacc[8][4];
#pragma unroll
    for (int nt = 0; nt < 8; nt++)
#pragma unroll
        for (int e = 0; e < 4; e++) oacc[nt][e] = 0.f;
    float mrow0 = -1e30f, mrow1 = -1e30f, lrow0 = 0.f, lrow1 = 0.f;

    const __nv_bfloat16* kHb = kH + kvh * DH;
    const __nv_bfloat16* kLb = kL + kvh * DH;
    const __nv_bfloat16* vHb = vH + ((size_t)kvh * DH) * S_LEN;
    const __nv_bfloat16* vLb = vL + ((size_t)kvh * DH) * S_LEN;

    auto load_tile = [&](int s, int j0) {
        __nv_bfloat16* base = smem + s * 4 * ATILE;
#pragma unroll
        for (int it = 0; it < 4; it++) {
            int slot = tid + 128 * it;
            int row = slot >> 3;
            int c   = (slot & 7) * 8;
            uint32_t da = (uint32_t)__cvta_generic_to_shared(base + row * ATS + c);
            cp16(da,             &kHb[(size_t)(j0 + row) * KVDIM + c]);
            cp16(da + 2*ATILE,   &kLb[(size_t)(j0 + row) * KVDIM + c]);
            cp16(da + 4*ATILE,   &vHb[(size_t)row * S_LEN + j0 + c]);
            cp16(da + 6*ATILE,   &vLb[(size_t)row * S_LEN + j0 + c]);
        }
    };

    load_tile(0, 0);
    CP_COMMIT();

    int s = 0;
    for (int j0 = 0; j0 <= q0; j0 += 64) {
        if (j0 + 64 <= q0) load_tile(s ^ 1, j0 + 64);
        CP_COMMIT();
        CP_WAIT1();
        __syncthreads();

        uint32_t sb  = su + s * (4 * ATILE * 2);
        uint32_t aKH = sb,              aKL = sb + 2 * ATILE;
        uint32_t aVH = sb + 4 * ATILE,  aVL = sb + 6 * ATILE;

        float sc[8][4];
#pragma unroll
        for (int nt = 0; nt < 8; nt++)
#pragma unroll
            for (int e = 0; e < 4; e++) sc[nt][e] = 0.f;

#pragma unroll
        for (int kc = 0; kc < 4; kc++)
#pragma unroll
            for (int p = 0; p < 4; p++) {
                uint32_t b00, b01, b10, b11;
                LDSM4(b00, b01, b10, b11, aKH + offK[p] + kc * 32);
                MMA_BF16(sc[2*p],     aH[kc], b00, b01);
                MMA_BF16(sc[2*p],     aL[kc], b00, b01);
                MMA_BF16(sc[2*p + 1], aH[kc], b10, b11);
                MMA_BF16(sc[2*p + 1], aL[kc], b10, b11);
                uint32_t c00, c01, c10, c11;
                LDSM4(c00, c01, c10, c11, aKL + offK[p] + kc * 32);
                MMA_BF16(sc[2*p],     aH[kc], c00, c01);
                MMA_BF16(sc[2*p + 1], aH[kc], c10, c11);
            }

        if (j0 == q0) {
#pragma unroll
            for (int nt = 0; nt < 8; nt++) {
                int col = j0 + nt * 8 + fc;
                int r0 = qrow + fr, r1 = r0 + 8;
                if (col     > r0) sc[nt][0] = -1e30f;
                if (col + 1 > r0) sc[nt][1] = -1e30f;
                if (col     > r1) sc[nt][2] = -1e30f;
                if (col + 1 > r1) sc[nt][3] = -1e30f;
            }
        }

        float mc0 = -1e30f, mc1 = -1e30f;
#pragma unroll
        for (int nt = 0; nt < 8; nt++) {
            mc0 = fmaxf(mc0, fmaxf(sc[nt][0], sc[nt][1]));
            mc1 = fmaxf(mc1, fmaxf(sc[nt][2], sc[nt][3]));
        }
        mc0 = fmaxf(mc0, __shfl_xor_sync(0xffffffffu, mc0, 1));
        mc0 = fmaxf(mc0, __shfl_xor_sync(0xffffffffu, mc0, 2));
        mc1 = fmaxf(mc1, __shfl_xor_sync(0xffffffffu, mc1, 1));
        mc1 = fmaxf(mc1, __shfl_xor_sync(0xffffffffu, mc1, 2));

        float mn0 = fmaxf(mrow0, mc0), mn1 = fmaxf(mrow1, mc1);
        float scale0 = __expf(mrow0 - mn0), scale1 = __expf(mrow1 - mn1);
        mrow0 = mn0; mrow1 = mn1;
#pragma unroll
        for (int nt = 0; nt < 8; nt++) {
            oacc[nt][0] *= scale0; oacc[nt][1] *= scale0;
            oacc[nt][2] *= scale1; oacc[nt][3] *= scale1;
        }
        float rs0 = 0.f, rs1 = 0.f;
#pragma unroll
        for (int nt = 0; nt < 8; nt++) {
            sc[nt][0] = __expf(sc[nt][0] - mn0);
            sc[nt][1] = __expf(sc[nt][1] - mn0);
            sc[nt][2] = __expf(sc[nt][2] - mn1);
            sc[nt][3] = __expf(sc[nt][3] - mn1);
            rs0 += sc[nt][0] + sc[nt][1];
            rs1 += sc[nt][2] + sc[nt][3];
        }
        rs0 += __shfl_xor_sync(0xffffffffu, rs0, 1);
        rs0 += __shfl_xor_sync(0xffffffffu, rs0, 2);
        rs1 += __shfl_xor_sync(0xffffffffu, rs1, 1);
        rs1 += __shfl_xor_sync(0xffffffffu, rs1, 2);
        lrow0 = lrow0 * scale0 + rs0;
        lrow1 = lrow1 * scale1 + rs1;

#pragma unroll
        for (int kc = 0; kc < 4; kc++) {
            uint32_t ph[4], pl[4];
            split2(sc[2 * kc][0],     sc[2 * kc][1],     ph[0], pl[0]);
            split2(sc[2 * kc][2],     sc[2 * kc][3],     ph[1], pl[1]);
            split2(sc[2 * kc + 1][0], sc[2 * kc + 1][1], ph[2], pl[2]);
            split2(sc[2 * kc + 1][2], sc[2 * kc + 1][3], ph[3], pl[3]);
#pragma unroll
            for (int p = 0; p < 4; p++) {
                uint32_t b00, b01, b10, b11;
                LDSM4(b00, b01, b10, b11, aVH + offK[p] + kc * 32);
                MMA_BF16(oacc[2*p],     ph, b00, b01);
                MMA_BF16(oacc[2*p],     pl, b00, b01);
                MMA_BF16(oacc[2*p + 1], ph, b10, b11);
                MMA_BF16(oacc[2*p + 1], pl, b10, b11);
                uint32_t c00, c01, c10, c11;
                LDSM4(c00, c01, c10, c11, aVL + offK[p] + kc * 32);
                MMA_BF16(oacc[2*p],     ph, c00, c01);
                MMA_BF16(oacc[2*p + 1], ph, c10, c11);
            }
        }
        __syncthreads();
        s ^= 1;
    }

    float inv0 = 1.f / lrow0, inv1 = 1.f / lrow1;
    size_t o0 = (size_t)(qrow + fr) * HQ + h * DH + fc;
#pragma unroll
    for (int nt = 0; nt < 8; nt++) {
        uint32_t h0, l0, h1, l1;
        split2(oacc[nt][0] * inv0, oacc[nt][1] * inv0, h0, l0);
        split2(oacc[nt][2] * inv1, oacc[nt][3] * inv1, h1, l1);
        *(uint32_t*)&oH[o0 + nt * 8]          = h0;
        *(uint32_t*)&oL[o0 + nt * 8]          = l0;
        *(uint32_t*)&oH[o0 + 8 * HQ + nt * 8] = h1;
        *(uint32_t*)&oL[o0 + 8 * HQ + nt * 8] = l1;
    }
}

// ---------------- launch ----------------
extern "C" void kernel_launch(void* const* d_in, const int* in_sizes, int n_in,
                              void* d_out, int out_size)
{
    const float* hs   = (const float*)d_in[0];
    const float* cosb = (const float*)d_in[3];
    const float* sinb = (const float*)d_in[4];
    const float* wq   = (const float*)d_in[5];
    const float* wk   = (const float*)d_in[6];
    const float* wv   = (const float*)d_in[7];
    const float* wd   = (const float*)d_in[8];
    float* out = (float*)d_out;

    float *pq, *pk, *pv;
    __nv_bfloat16 *hsH, *hsL, *aoH, *aoL, *qsH, *qsL, *ksH, *ksL, *vtH, *vtL;
    __nv_bfloat16 *wqH, *wqL, *wdH, *wdL, *wkH, *wkL, *wvH, *wvL;
    cudaGetSymbolAddress((void**)&pq,  g_q);
    cudaGetSymbolAddress((void**)&pk,  g_k);
    cudaGetSymbolAddress((void**)&pv,  g_v);
    cudaGetSymbolAddress((void**)&hsH, g_hsH); cudaGetSymbolAddress((void**)&hsL, g_hsL);
    cudaGetSymbolAddress((void**)&aoH, g_aoH); cudaGetSymbolAddress((void**)&aoL, g_aoL);
    cudaGetSymbolAddress((void**)&qsH, g_qsH); cudaGetSymbolAddress((void**)&qsL, g_qsL);
    cudaGetSymbolAddress((void**)&ksH, g_ksH); cudaGetSymbolAddress((void**)&ksL, g_ksL);
    cudaGetSymbolAddress((void**)&vtH, g_vtH); cudaGetSymbolAddress((void**)&vtL, g_vtL);
    cudaGetSymbolAddress((void**)&wqH, g_wqH); cudaGetSymbolAddress((void**)&wqL, g_wqL);
    cudaGetSymbolAddress((void**)&wdH, g_wdH); cudaGetSymbolAddress((void**)&wdL, g_wdL);
    cudaGetSymbolAddress((void**)&wkH, g_wkH); cudaGetSymbolAddress((void**)&wkL, g_wkL);
    cudaGetSymbolAddress((void**)&wvH, g_wvH); cudaGetSymbolAddress((void**)&wvL, g_wvL);

    static cudaStream_t st1 = nullptr, st2 = nullptr;
    static cudaEvent_t evRoot, evHs, evWq, evKV, evWd, evA0, evOut0;
    if (!st1) {
        cudaStreamCreateWithFlags(&st1, cudaStreamNonBlocking);
        cudaStreamCreateWithFlags(&st2, cudaStreamNonBlocking);
        cudaEventCreateWithFlags(&evRoot, cudaEventDisableTiming);
        cudaEventCreateWithFlags(&evHs,   cudaEventDisableTiming);
        cudaEventCreateWithFlags(&evWq,   cudaEventDisableTiming);
        cudaEventCreateWithFlags(&evKV,   cudaEventDisableTiming);
        cudaEventCreateWithFlags(&evWd,   cudaEventDisableTiming);
        cudaEventCreateWithFlags(&evA0,   cudaEventDisableTiming);
        cudaEventCreateWithFlags(&evOut0, cudaEventDisableTiming);
        cudaFuncSetAttribute(gemm3_kernel,
                             cudaFuncAttributeMaxDynamicSharedMemorySize, GEMM_SMEM);
        cudaFuncSetAttribute(gemm3_kv_kernel,
                             cudaFuncAttributeMaxDynamicSharedMemorySize, GEMM_SMEM);
        cudaFuncSetAttribute(attn_mma_kernel,
                             cudaFuncAttributeMaxDynamicSharedMemorySize, ATT_SMEM);
    }

    // fork side streams off the capture-origin stream
    cudaEventRecord(evRoot, 0);
    cudaStreamWaitEvent(st1, evRoot, 0);
    cudaStreamWaitEvent(st2, evRoot, 0);

    // ---- stream 2: wq split (concurrent with hs split), then wd split ----
    {
        int n4 = HQ * HQ / 4;
        split_kernel<<<(n4 + 255) / 256, 256, 0, st2>>>(wq, wqH, wqL, n4);
        cudaEventRecord(evWq, st2);
        split_kernel<<<(n4 + 255) / 256, 256, 0, st2>>>(wd, wdH, wdL, n4);
        cudaEventRecord(evWd, st2);
    }

    // ---- stream 0 (critical path): hs split -> Q gemm -> rope_q ----
    {
        int n4 = MROWS * HQ / 4;
        split_kernel<<<(n4 + 255) / 256, 256>>>(hs, hsH, hsL, n4);
        cudaEventRecord(evHs, 0);
    }
    cudaStreamWaitEvent(0, evWq, 0);
    gemm3_kernel<<<dim3(HQ / GBN, MROWS / GBM), 256, GEMM_SMEM>>>(hsH, hsL, wqH, wqL, pq, HQ, HQ);
    {
        int tq = MROWS * NH * (DH / 2);
        rope_split_kernel<<<(tq + 255) / 256, 256>>>(pq, cosb, sinb, qsH, qsL, NH, 0.125f);
    }

    // ---- stream 1: wk/wv splits -> fused KV gemm -> rope_k + V transpose ----
    {
        int n4 = KVDIM * HQ / 4;
        split_kernel<<<(n4 + 255) / 256, 256, 0, st1>>>(wk, wkH, wkL, n4);
        split_kernel<<<(n4 + 255) / 256, 256, 0, st1>>>(wv, wvH, wvL, n4);
        cudaStreamWaitEvent(st1, evHs, 0);
        gemm3_kv_kernel<<<dim3(8, MROWS / GBM), 256, GEMM_SMEM, st1>>>(
            hsH, hsL, wkH, wkL, wvH, wvL, pk, pv);
        int tk = MROWS * NKV * (DH / 2);
        rope_split_kernel<<<(tk + 255) / 256, 256, 0, st1>>>(pk, cosb, sinb, ksH, ksL, NKV, 1.0f);
        splitvt_kernel<<<dim3(S_LEN / 64, NKV, BDIM), 256, 0, st1>>>(pv, vtH, vtL);
        cudaEventRecord(evKV, st1);
    }

    // ---- attention batch 0, then batch 1 (stream 0) ----
    cudaStreamWaitEvent(0, evKV, 0);
    attn_mma_kernel<<<dim3(S_LEN / 64, NH, 1), 128, ATT_SMEM>>>(
        qsH, qsL, ksH, ksL, vtH, vtL, aoH, aoL);
    cudaEventRecord(evA0, 0);
    attn_mma_kernel<<<dim3(S_LEN / 64, NH, 1), 128, ATT_SMEM>>>(
        qsH + (size_t)S_LEN * HQ, qsL + (size_t)S_LEN * HQ,
        ksH + (size_t)S_LEN * KVDIM, ksL + (size_t)S_LEN * KVDIM,
        vtH + (size_t)S_LEN * KVDIM, vtL + (size_t)S_LEN * KVDIM,
        aoH + (size_t)S_LEN * HQ, aoL + (size_t)S_LEN * HQ);

    // ---- out-proj half 0 (rows 0..1023) on stream 2, overlapping attention b=1 ----
    cudaStreamWaitEvent(st2, evA0, 0);
    gemm3_kernel<<<dim3(HQ / GBN, S_LEN / GBM), 256, GEMM_SMEM, st2>>>(
        aoH, aoL, wdH, wdL, out, HQ, HQ);
    cudaEventRecord(evOut0, st2);

    // ---- out-proj half 1 (rows 1024..2047) on stream 0 ----
    cudaStreamWaitEvent(0, evWd, 0);
    gemm3_kernel<<<dim3(HQ / GBN, S_LEN / GBM), 256, GEMM_SMEM>>>(
        aoH + (size_t)S_LEN * HQ, aoL + (size_t)S_LEN * HQ, wdH, wdL,
        out + (size_t)S_LEN * HQ, HQ, HQ);
    cudaStreamWaitEvent(0, evOut0, 0);
}

// round 15
// speedup vs baseline: 1.5434x; 1.5434x over previous
#include <cuda_runtime.h>
#include <cuda_bf16.h>
#include <cstdint>

#define S_LEN 1024
#define BDIM  2
#define HQ    4096
#define NKV   8
#define NH    64
#define DH    64
#define MROWS (BDIM * S_LEN)   // 2048
#define KVDIM (NKV * DH)       // 512

// ---------------- scratch (device globals; no allocs allowed) ----------------
__device__ float g_q [MROWS * HQ];
__device__ float g_k [MROWS * KVDIM];
__device__ float g_v [MROWS * KVDIM];
__device__ __nv_bfloat16 g_hsH[MROWS * HQ], g_hsL[MROWS * HQ];
__device__ __nv_bfloat16 g_aoH[MROWS * HQ], g_aoL[MROWS * HQ];
__device__ __nv_bfloat16 g_qsH[MROWS * HQ], g_qsL[MROWS * HQ];
__device__ __nv_bfloat16 g_ksH[MROWS * KVDIM], g_ksL[MROWS * KVDIM];
__device__ __nv_bfloat16 g_vtH[MROWS * KVDIM], g_vtL[MROWS * KVDIM];
__device__ __nv_bfloat16 g_wqH[HQ * HQ],    g_wqL[HQ * HQ];
__device__ __nv_bfloat16 g_wdH[HQ * HQ],    g_wdL[HQ * HQ];
__device__ __nv_bfloat16 g_wkH[KVDIM * HQ], g_wkL[KVDIM * HQ];
__device__ __nv_bfloat16 g_wvH[KVDIM * HQ], g_wvL[KVDIM * HQ];

// ---------------- helpers ----------------
__device__ __forceinline__ void split2(float x, float y, uint32_t& hi, uint32_t& lo)
{
    __nv_bfloat16 hx = __float2bfloat16(x), hy = __float2bfloat16(y);
    __nv_bfloat16 lx = __float2bfloat16(x - __bfloat162float(hx));
    __nv_bfloat16 ly = __float2bfloat16(y - __bfloat162float(hy));
    __nv_bfloat162 H = __halves2bfloat162(hx, hy);
    __nv_bfloat162 L = __halves2bfloat162(lx, ly);
    hi = *(uint32_t*)&H; lo = *(uint32_t*)&L;
}

#define MMA_BF16(d, av, b0, b1) \
    asm volatile("mma.sync.aligned.m16n8k16.row.col.f32.bf16.bf16.f32 " \
                 "{%0,%1,%2,%3}, {%4,%5,%6,%7}, {%8,%9}, {%0,%1,%2,%3};\n" \
                 : "+f"(d[0]), "+f"(d[1]), "+f"(d[2]), "+f"(d[3]) \
                 : "r"(av[0]), "r"(av[1]), "r"(av[2]), "r"(av[3]), \
                   "r"(b0), "r"(b1))

#define LDSM4(d0, d1, d2, d3, a) \
    asm volatile("ldmatrix.sync.aligned.m8n8.x4.shared.b16 {%0,%1,%2,%3}, [%4];\n" \
                 : "=r"(d0), "=r"(d1), "=r"(d2), "=r"(d3) : "r"(a))

__device__ __forceinline__ void cp16(uint32_t sa, const void* g)
{
    asm volatile("cp.async.cg.shared.global [%0], [%1], 16;\n" :: "r"(sa), "l"(g));
}
#define CP_COMMIT() asm volatile("cp.async.commit_group;\n" ::: "memory")
#define CP_WAIT1()  asm volatile("cp.async.wait_group 1;\n" ::: "memory")

// ---------------- fp32 -> (hi, lo) bf16 split ----------------
__global__ void __launch_bounds__(256) split_kernel(
    const float* __restrict__ x, __nv_bfloat16* __restrict__ hi,
    __nv_bfloat16* __restrict__ lo, int n4)
{
    int i = blockIdx.x * blockDim.x + threadIdx.x;
    if (i >= n4) return;
    float4 v = ((const float4*)x)[i];
    uint32_t h0, l0, h1, l1;
    split2(v.x, v.y, h0, l0);
    split2(v.z, v.w, h1, l1);
    uint32_t* hp = (uint32_t*)hi + (size_t)i * 2;
    uint32_t* lp = (uint32_t*)lo + (size_t)i * 2;
    hp[0] = h0; hp[1] = h1;
    lp[0] = l0; lp[1] = l1;
}

// ---------------- bf16 split-GEMM, cp.async double-buffered, ldmatrix ----------------
// C[m,n] = sum_k A[m,k]*W[n,k];  C = Ah*Bh + Al*Bh + Ah*Bl  (fp32 accum)
#define GBM 128
#define GBN 128
#define GBK 32
#define ASTR 40
#define GTILE (GBM * ASTR)            // elements per array per stage
#define GEMM_SMEM (2 * 4 * GTILE * 2) // bytes

__device__ __forceinline__ void gemm3_body(
    const __nv_bfloat16* __restrict__ AH, const __nv_bfloat16* __restrict__ AL,
    const __nv_bfloat16* __restrict__ BH, const __nv_bfloat16* __restrict__ BL,
    float* __restrict__ C, int K, int N, int m0, int n0, __nv_bfloat16* smem)
{
    const int tid  = threadIdx.x;
    const int wid  = tid >> 5;
    const int lane = tid & 31;
    const int wm = (wid & 1) * 64;
    const int wn = (wid >> 1) * 32;
    const int fr = lane >> 2;
    const int fc = (lane & 3) * 2;

    float acc[4][4][4];
#pragma unroll
    for (int mt = 0; mt < 4; mt++)
#pragma unroll
        for (int nt = 0; nt < 4; nt++)
#pragma unroll
            for (int e = 0; e < 4; e++) acc[mt][nt][e] = 0.f;

    int offA[4], offB[2];
#pragma unroll
    for (int mt = 0; mt < 4; mt++)
        offA[mt] = ((wm + mt * 16 + (lane & 7) + ((lane >> 3) & 1) * 8) * ASTR
                    + (lane >> 4) * 8) * 2;
#pragma unroll
    for (int p = 0; p < 2; p++)
        offB[p] = ((wn + p * 16 + (lane >> 4) * 8 + (lane & 7)) * ASTR
                   + ((lane >> 3) & 1) * 8) * 2;

    const uint32_t su = (uint32_t)__cvta_generic_to_shared(smem);

    auto load_stage = [&](int s, int k0) {
        __nv_bfloat16* base = smem + s * 4 * GTILE;
#pragma unroll
        for (int r = 0; r < 2; r++) {
            int slot = tid + 256 * r;
            int row  = slot >> 2;
            int q    = (slot & 3) * 8;
            size_t ga = (size_t)(m0 + row) * K + k0 + q;
            size_t gb = (size_t)(n0 + row) * K + k0 + q;
            uint32_t da = (uint32_t)__cvta_generic_to_shared(base + row * ASTR + q);
            cp16(da,             AH + ga);
            cp16(da + 2*GTILE,   AL + ga);
            cp16(da + 4*GTILE,   BH + gb);
            cp16(da + 6*GTILE,   BL + gb);
        }
    };

    load_stage(0, 0);
    CP_COMMIT();

    int s = 0;
    for (int k0 = 0; k0 < K; k0 += GBK) {
        if (k0 + GBK < K) load_stage(s ^ 1, k0 + GBK);
        CP_COMMIT();
        CP_WAIT1();
        __syncthreads();

        uint32_t sb  = su + s * (4 * GTILE * 2);
        uint32_t aAH = sb,              aAL = sb + 2 * GTILE;
        uint32_t aBH = sb + 4 * GTILE,  aBL = sb + 6 * GTILE;

#pragma unroll
        for (int kk = 0; kk < GBK; kk += 16) {
            uint32_t bh[4][2], bl[4][2];
            LDSM4(bh[0][0], bh[0][1], bh[1][0], bh[1][1], aBH + offB[0] + kk * 2);
            LDSM4(bh[2][0], bh[2][1], bh[3][0], bh[3][1], aBH + offB[1] + kk * 2);
            LDSM4(bl[0][0], bl[0][1], bl[1][0], bl[1][1], aBL + offB[0] + kk * 2);
            LDSM4(bl[2][0], bl[2][1], bl[3][0], bl[3][1], aBL + offB[1] + kk * 2);
            uint32_t a[4][4];
#pragma unroll
            for (int mt = 0; mt < 4; mt++)
                LDSM4(a[mt][0], a[mt][1], a[mt][2], a[mt][3], aAH + offA[mt] + kk * 2);
#pragma unroll
            for (int mt = 0; mt < 4; mt++)
#pragma unroll
                for (int nt = 0; nt < 4; nt++) {
                    MMA_BF16(acc[mt][nt], a[mt], bh[nt][0], bh[nt][1]);
                    MMA_BF16(acc[mt][nt], a[mt], bl[nt][0], bl[nt][1]);
                }
#pragma unroll
            for (int mt = 0; mt < 4; mt++)
                LDSM4(a[mt][0], a[mt][1], a[mt][2], a[mt][3], aAL + offA[mt] + kk * 2);
#pragma unroll
            for (int mt = 0; mt < 4; mt++)
#pragma unroll
                for (int nt = 0; nt < 4; nt++)
                    MMA_BF16(acc[mt][nt], a[mt], bh[nt][0], bh[nt][1]);
        }
        __syncthreads();
        s ^= 1;
    }

#pragma unroll
    for (int mt = 0; mt < 4; mt++)
#pragma unroll
        for (int nt = 0; nt < 4; nt++) {
            size_t base = (size_t)(m0 + wm + mt * 16 + fr) * N + n0 + wn + nt * 8 + fc;
            *(float2*)&C[base]                 = make_float2(acc[mt][nt][0], acc[mt][nt][1]);
            *(float2*)&C[base + 8 * (size_t)N] = make_float2(acc[mt][nt][2], acc[mt][nt][3]);
        }
}

__global__ void __launch_bounds__(256, 2) gemm3_kernel(
    const __nv_bfloat16* __restrict__ AH, const __nv_bfloat16* __restrict__ AL,
    const __nv_bfloat16* __restrict__ BH, const __nv_bfloat16* __restrict__ BL,
    float* __restrict__ C, int K, int N)
{
    extern __shared__ __nv_bfloat16 smem[];
    gemm3_body(AH, AL, BH, BL, C, K, N, blockIdx.y * GBM, blockIdx.x * GBN, smem);
}

// fused K+V projection: grid.x = 8; 0..3 -> K, 4..7 -> V
__global__ void __launch_bounds__(256, 2) gemm3_kv_kernel(
    const __nv_bfloat16* __restrict__ AH, const __nv_bfloat16* __restrict__ AL,
    const __nv_bfloat16* __restrict__ KH, const __nv_bfloat16* __restrict__ KL,
    const __nv_bfloat16* __restrict__ VH, const __nv_bfloat16* __restrict__ VL,
    float* __restrict__ Ck, float* __restrict__ Cv)
{
    extern __shared__ __nv_bfloat16 smem[];
    const __nv_bfloat16 *BH, *BL;
    float* C;
    int n0;
    if (blockIdx.x < 4) { BH = KH; BL = KL; C = Ck; n0 = blockIdx.x * GBN; }
    else                { BH = VH; BL = VL; C = Cv; n0 = (blockIdx.x - 4) * GBN; }
    gemm3_body(AH, AL, BH, BL, C, HQ, KVDIM, blockIdx.y * GBM, n0, smem);
}

// ---------------- RoPE + hi/lo split ----------------
__global__ void rope_split_kernel(
    const float* __restrict__ p, const float* __restrict__ cosb,
    const float* __restrict__ sinb, __nv_bfloat16* __restrict__ outH,
    __nv_bfloat16* __restrict__ outL, int nheads, float scl)
{
    int idx = blockIdx.x * blockDim.x + threadIdx.x;
    int total = MROWS * nheads * (DH / 2);
    if (idx >= total) return;
    int d  = idx & 31;
    int h  = (idx >> 5) % nheads;
    int bs = idx / (nheads * 32);
    int s  = bs & (S_LEN - 1);
    size_t base = (size_t)bs * nheads * DH + h * DH;
    float x1 = p[base + d];
    float x2 = p[base + d + 32];
    float c1 = cosb[s * DH + d],      s1 = sinb[s * DH + d];
    float c2 = cosb[s * DH + d + 32], s2 = sinb[s * DH + d + 32];
    float y1 = (x1 * c1 - x2 * s1) * scl;
    float y2 = (x2 * c2 + x1 * s2) * scl;
    __nv_bfloat16 h1 = __float2bfloat16(y1);
    __nv_bfloat16 h2 = __float2bfloat16(y2);
    outH[base + d]      = h1;
    outH[base + d + 32] = h2;
    outL[base + d]      = __float2bfloat16(y1 - __bfloat162float(h1));
    outL[base + d + 32] = __float2bfloat16(y2 - __bfloat162float(h2));
}

// ---------------- V split + transpose ----------------
__global__ void __launch_bounds__(256) splitvt_kernel(
    const float* __restrict__ v, __nv_bfloat16* __restrict__ vtH,
    __nv_bfloat16* __restrict__ vtL)
{
    __shared__ float sm[64][65];
    const int s0  = blockIdx.x * 64;
    const int kvh = blockIdx.y;
    const int b   = blockIdx.z;
    const int tid = threadIdx.x;

#pragma unroll
    for (int r = 0; r < 16; r++) {
        int slot = tid + 256 * r;
        int sl = slot >> 6;
        int d  = slot & 63;
        sm[d][sl] = v[(size_t)(b * S_LEN + s0 + sl) * KVDIM + kvh * DH + d];
    }
    __syncthreads();
#pragma unroll
    for (int r = 0; r < 16; r++) {
        int slot = tid + 256 * r;
        int d  = slot >> 6;
        int sl = slot & 63;
        float x = sm[d][sl];
        __nv_bfloat16 h = __float2bfloat16(x);
        size_t o = ((size_t)((b * NKV + kvh) * DH + d)) * S_LEN + s0 + sl;
        vtH[o] = h;
        vtL[o] = __float2bfloat16(x - __bfloat162float(h));
    }
}

// ---------------- Flash attention: tensor cores + cp.async pipeline + ldmatrix ----------------
#define ATS 72
#define ATILE (64 * ATS)               // elements per array per stage
#define ATT_SMEM (2 * 4 * ATILE * 2)   // bytes

__global__ void __launch_bounds__(128) attn_mma_kernel(
    const __nv_bfloat16* __restrict__ qH, const __nv_bfloat16* __restrict__ qL,
    const __nv_bfloat16* __restrict__ kH, const __nv_bfloat16* __restrict__ kL,
    const __nv_bfloat16* __restrict__ vH, const __nv_bfloat16* __restrict__ vL,
    __nv_bfloat16* __restrict__ oH, __nv_bfloat16* __restrict__ oL)
{
    extern __shared__ __nv_bfloat16 smem[];

    const int b   = blockIdx.z;
    const int h   = blockIdx.y;
    const int kvh = h >> 3;
    // LPT: heavy causal tiles launch first, light tiles backfill the tail
    const int q0  = (gridDim.x - 1 - blockIdx.x) * 64;
    const int tid  = threadIdx.x;
    const int w    = tid >> 5;
    const int lane = tid & 31;
    const int fr = lane >> 2;
    const int fc = (lane & 3) * 2;
    const int qrow = q0 + w * 16;

    int offK[4];
#pragma unroll
    for (int p = 0; p < 4; p++)
        offK[p] = ((p * 16 + (lane >> 4) * 8 + (lane & 7)) * ATS
                   + ((lane >> 3) & 1) * 8) * 2;

    const uint32_t su = (uint32_t)__cvta_generic_to_shared(smem);

    uint32_t aH[4][4], aL[4][4];
    {
        const __nv_bfloat16* p0 = qH + (size_t)(b * S_LEN + qrow + fr) * HQ + h * DH + fc;
        const __nv_bfloat16* p1 = qL + (size_t)(b * S_LEN + qrow + fr) * HQ + h * DH + fc;
#pragma unroll
        for (int kc = 0; kc < 4; kc++) {
            aH[kc][0] = *(const uint32_t*)(p0 + kc * 16);
            aH[kc][1] = *(const uint32_t*)(p0 + kc * 16 + 8 * HQ);
            aH[kc][2] = *(const uint32_t*)(p0 + kc * 16 + 8);
            aH[kc][3] = *(const uint32_t*)(p0 + kc * 16 + 8 * HQ + 8);
            aL[kc][0] = *(const uint32_t*)(p1 + kc * 16);
            aL[kc][1] = *(const uint32_t*)(p1 + kc * 16 + 8 * HQ);
            aL[kc][2] = *(const uint32_t*)(p1 + kc * 16 + 8);
            aL[kc][3] = *(const uint32_t*)(p1 + kc * 16 + 8 * HQ + 8);
        }
    }

    float oacc[8][4];
#pragma unroll
    for (int nt = 0; nt < 8; nt++)
#pragma unroll
        for (int e = 0; e < 4; e++) oacc[nt][e] = 0.f;
    float mrow0 = -1e30f, mrow1 = -1e30f, lrow0 = 0.f, lrow1 = 0.f;

    const __nv_bfloat16* kHb = kH + (size_t)b * S_LEN * KVDIM + kvh * DH;
    const __nv_bfloat16* kLb = kL + (size_t)b * S_LEN * KVDIM + kvh * DH;
    const __nv_bfloat16* vHb = vH + ((size_t)(b * NKV + kvh) * DH) * S_LEN;
    const __nv_bfloat16* vLb = vL + ((size_t)(b * NKV + kvh) * DH) * S_LEN;

    auto load_tile = [&](int s, int j0) {
        __nv_bfloat16* base = smem + s * 4 * ATILE;
#pragma unroll
        for (int it = 0; it < 4; it++) {
            int slot = tid + 128 * it;
            int row = slot >> 3;
            int c   = (slot & 7) * 8;
            uint32_t da = (uint32_t)__cvta_generic_to_shared(base + row * ATS + c);
            cp16(da,             &kHb[(size_t)(j0 + row) * KVDIM + c]);
            cp16(da + 2*ATILE,   &kLb[(size_t)(j0 + row) * KVDIM + c]);
            cp16(da + 4*ATILE,   &vHb[(size_t)row * S_LEN + j0 + c]);
            cp16(da + 6*ATILE,   &vLb[(size_t)row * S_LEN + j0 + c]);
        }
    };

    load_tile(0, 0);
    CP_COMMIT();

    int s = 0;
    for (int j0 = 0; j0 <= q0; j0 += 64) {
        if (j0 + 64 <= q0) load_tile(s ^ 1, j0 + 64);
        CP_COMMIT();
        CP_WAIT1();
        __syncthreads();

        uint32_t sb  = su + s * (4 * ATILE * 2);
        uint32_t aKH = sb,              aKL = sb + 2 * ATILE;
        uint32_t aVH = sb + 4 * ATILE,  aVL = sb + 6 * ATILE;

        float sc[8][4];
#pragma unroll
        for (int nt = 0; nt < 8; nt++)
#pragma unroll
            for (int e = 0; e < 4; e++) sc[nt][e] = 0.f;

#pragma unroll
        for (int kc = 0; kc < 4; kc++)
#pragma unroll
            for (int p = 0; p < 4; p++) {
                uint32_t b00, b01, b10, b11;
                LDSM4(b00, b01, b10, b11, aKH + offK[p] + kc * 32);
                MMA_BF16(sc[2*p],     aH[kc], b00, b01);
                MMA_BF16(sc[2*p],     aL[kc], b00, b01);
                MMA_BF16(sc[2*p + 1], aH[kc], b10, b11);
                MMA_BF16(sc[2*p + 1], aL[kc], b10, b11);
                uint32_t c00, c01, c10, c11;
                LDSM4(c00, c01, c10, c11, aKL + offK[p] + kc * 32);
                MMA_BF16(sc[2*p],     aH[kc], c00, c01);
                MMA_BF16(sc[2*p + 1], aH[kc], c10, c11);
            }

        if (j0 == q0) {
#pragma unroll
            for (int nt = 0; nt < 8; nt++) {
                int col = j0 + nt * 8 + fc;
                int r0 = qrow + fr, r1 = r0 + 8;
                if (col     > r0) sc[nt][0] = -1e30f;
                if (col + 1 > r0) sc[nt][1] = -1e30f;
                if (col     > r1) sc[nt][2] = -1e30f;
                if (col + 1 > r1) sc[nt][3] = -1e30f;
            }
        }

        float mc0 = -1e30f, mc1 = -1e30f;
#pragma unroll
        for (int nt = 0; nt < 8; nt++) {
            mc0 = fmaxf(mc0, fmaxf(sc[nt][0], sc[nt][1]));
            mc1 = fmaxf(mc1, fmaxf(sc[nt][2], sc[nt][3]));
        }
        mc0 = fmaxf(mc0, __shfl_xor_sync(0xffffffffu, mc0, 1));
        mc0 = fmaxf(mc0, __shfl_xor_sync(0xffffffffu, mc0, 2));
        mc1 = fmaxf(mc1, __shfl_xor_sync(0xffffffffu, mc1, 1));
        mc1 = fmaxf(mc1, __shfl_xor_sync(0xffffffffu, mc1, 2));

        float mn0 = fmaxf(mrow0, mc0), mn1 = fmaxf(mrow1, mc1);
        float scale0 = __expf(mrow0 - mn0), scale1 = __expf(mrow1 - mn1);
        mrow0 = mn0; mrow1 = mn1;
#pragma unroll
        for (int nt = 0; nt < 8; nt++) {
            oacc[nt][0] *= scale0; oacc[nt][1] *= scale0;
            oacc[nt][2] *= scale1; oacc[nt][3] *= scale1;
        }
        float rs0 = 0.f, rs1 = 0.f;
#pragma unroll
        for (int nt = 0; nt < 8; nt++) {
            sc[nt][0] = __expf(sc[nt][0] - mn0);
            sc[nt][1] = __expf(sc[nt][1] - mn0);
            sc[nt][2] = __expf(sc[nt][2] - mn1);
            sc[nt][3] = __expf(sc[nt][3] - mn1);
            rs0 += sc[nt][0] + sc[nt][1];
            rs1 += sc[nt][2] + sc[nt][3];
        }
        rs0 += __shfl_xor_sync(0xffffffffu, rs0, 1);
        rs0 += __shfl_xor_sync(0xffffffffu, rs0, 2);
        rs1 += __shfl_xor_sync(0xffffffffu, rs1, 1);
        rs1 += __shfl_xor_sync(0xffffffffu, rs1, 2);
        lrow0 = lrow0 * scale0 + rs0;
        lrow1 = lrow1 * scale1 + rs1;

#pragma unroll
        for (int kc = 0; kc < 4; kc++) {
            uint32_t ph[4], pl[4];
            split2(sc[2 * kc][0],     sc[2 * kc][1],     ph[0], pl[0]);
            split2(sc[2 * kc][2],     sc[2 * kc][3],     ph[1], pl[1]);
            split2(sc[2 * kc + 1][0], sc[2 * kc + 1][1], ph[2], pl[2]);
            split2(sc[2 * kc + 1][2], sc[2 * kc + 1][3], ph[3], pl[3]);
#pragma unroll
            for (int p = 0; p < 4; p++) {
                uint32_t b00, b01, b10, b11;
                LDSM4(b00, b01, b10, b11, aVH + offK[p] + kc * 32);
                MMA_BF16(oacc[2*p],     ph, b00, b01);
                MMA_BF16(oacc[2*p],     pl, b00, b01);
                MMA_BF16(oacc[2*p + 1], ph, b10, b11);
                MMA_BF16(oacc[2*p + 1], pl, b10, b11);
                uint32_t c00, c01, c10, c11;
                LDSM4(c00, c01, c10, c11, aVL + offK[p] + kc * 32);
                MMA_BF16(oacc[2*p],     ph, c00, c01);
                MMA_BF16(oacc[2*p + 1], ph, c10, c11);
            }
        }
        __syncthreads();
        s ^= 1;
    }

    float inv0 = 1.f / lrow0, inv1 = 1.f / lrow1;
    size_t o0 = (size_t)(b * S_LEN + qrow + fr) * HQ + h * DH + fc;
#pragma unroll
    for (int nt = 0; nt < 8; nt++) {
        uint32_t h0, l0, h1, l1;
        split2(oacc[nt][0] * inv0, oacc[nt][1] * inv0, h0, l0);
        split2(oacc[nt][2] * inv1, oacc[nt][3] * inv1, h1, l1);
        *(uint32_t*)&oH[o0 + nt * 8]          = h0;
        *(uint32_t*)&oL[o0 + nt * 8]          = l0;
        *(uint32_t*)&oH[o0 + 8 * HQ + nt * 8] = h1;
        *(uint32_t*)&oL[o0 + 8 * HQ + nt * 8] = l1;
    }
}

// ---------------- launch (exact R12 schedule) ----------------
extern "C" void kernel_launch(void* const* d_in, const int* in_sizes, int n_in,
                              void* d_out, int out_size)
{
    const float* hs   = (const float*)d_in[0];
    const float* cosb = (const float*)d_in[3];
    const float* sinb = (const float*)d_in[4];
    const float* wq   = (const float*)d_in[5];
    const float* wk   = (const float*)d_in[6];
    const float* wv   = (const float*)d_in[7];
    const float* wd   = (const float*)d_in[8];
    float* out = (float*)d_out;

    float *pq, *pk, *pv;
    __nv_bfloat16 *hsH, *hsL, *aoH, *aoL, *qsH, *qsL, *ksH, *ksL, *vtH, *vtL;
    __nv_bfloat16 *wqH, *wqL, *wdH, *wdL, *wkH, *wkL, *wvH, *wvL;
    cudaGetSymbolAddress((void**)&pq,  g_q);
    cudaGetSymbolAddress((void**)&pk,  g_k);
    cudaGetSymbolAddress((void**)&pv,  g_v);
    cudaGetSymbolAddress((void**)&hsH, g_hsH); cudaGetSymbolAddress((void**)&hsL, g_hsL);
    cudaGetSymbolAddress((void**)&aoH, g_aoH); cudaGetSymbolAddress((void**)&aoL, g_aoL);
    cudaGetSymbolAddress((void**)&qsH, g_qsH); cudaGetSymbolAddress((void**)&qsL, g_qsL);
    cudaGetSymbolAddress((void**)&ksH, g_ksH); cudaGetSymbolAddress((void**)&ksL, g_ksL);
    cudaGetSymbolAddress((void**)&vtH, g_vtH); cudaGetSymbolAddress((void**)&vtL, g_vtL);
    cudaGetSymbolAddress((void**)&wqH, g_wqH); cudaGetSymbolAddress((void**)&wqL, g_wqL);
    cudaGetSymbolAddress((void**)&wdH, g_wdH); cudaGetSymbolAddress((void**)&wdL, g_wdL);
    cudaGetSymbolAddress((void**)&wkH, g_wkH); cudaGetSymbolAddress((void**)&wkL, g_wkL);
    cudaGetSymbolAddress((void**)&wvH, g_wvH); cudaGetSymbolAddress((void**)&wvL, g_wvL);

    static cudaStream_t st1 = nullptr, st2 = nullptr;
    static cudaEvent_t evRoot, evHs, evKV, evWd;
    if (!st1) {
        cudaStreamCreateWithFlags(&st1, cudaStreamNonBlocking);
        cudaStreamCreateWithFlags(&st2, cudaStreamNonBlocking);
        cudaEventCreateWithFlags(&evRoot, cudaEventDisableTiming);
        cudaEventCreateWithFlags(&evHs,   cudaEventDisableTiming);
        cudaEventCreateWithFlags(&evKV,   cudaEventDisableTiming);
        cudaEventCreateWithFlags(&evWd,   cudaEventDisableTiming);
        cudaFuncSetAttribute(gemm3_kernel,
                             cudaFuncAttributeMaxDynamicSharedMemorySize, GEMM_SMEM);
        cudaFuncSetAttribute(gemm3_kv_kernel,
                             cudaFuncAttributeMaxDynamicSharedMemorySize, GEMM_SMEM);
        cudaFuncSetAttribute(attn_mma_kernel,
                             cudaFuncAttributeMaxDynamicSharedMemorySize, ATT_SMEM);
    }

    // fork side streams off the capture-origin stream
    cudaEventRecord(evRoot, 0);
    cudaStreamWaitEvent(st1, evRoot, 0);
    cudaStreamWaitEvent(st2, evRoot, 0);

    // ---- stream 0 (critical path): hs split -> Q gemm -> rope_q ----
    {
        int n4 = MROWS * HQ / 4;
        split_kernel<<<(n4 + 255) / 256, 256>>>(hs, hsH, hsL, n4);
        cudaEventRecord(evHs, 0);
        n4 = HQ * HQ / 4;
        split_kernel<<<(n4 + 255) / 256, 256>>>(wq, wqH, wqL, n4);
    }
    gemm3_kernel<<<dim3(HQ / GBN, MROWS / GBM), 256, GEMM_SMEM>>>(hsH, hsL, wqH, wqL, pq, HQ, HQ);
    {
        int tq = MROWS * NH * (DH / 2);
        rope_split_kernel<<<(tq + 255) / 256, 256>>>(pq, cosb, sinb, qsH, qsL, NH, 0.125f);
    }

    // ---- stream 1: wk/wv splits -> fused KV gemm -> rope_k + V transpose ----
    {
        int n4 = KVDIM * HQ / 4;
        split_kernel<<<(n4 + 255) / 256, 256, 0, st1>>>(wk, wkH, wkL, n4);
        split_kernel<<<(n4 + 255) / 256, 256, 0, st1>>>(wv, wvH, wvL, n4);
        cudaStreamWaitEvent(st1, evHs, 0);
        gemm3_kv_kernel<<<dim3(8, MROWS / GBM), 256, GEMM_SMEM, st1>>>(
            hsH, hsL, wkH, wkL, wvH, wvL, pk, pv);
        int tk = MROWS * NKV * (DH / 2);
        rope_split_kernel<<<(tk + 255) / 256, 256, 0, st1>>>(pk, cosb, sinb, ksH, ksL, NKV, 1.0f);
        splitvt_kernel<<<dim3(S_LEN / 64, NKV, BDIM), 256, 0, st1>>>(pv, vtH, vtL);
        cudaEventRecord(evKV, st1);
    }

    // ---- stream 2: wd split (needed only by out-proj) ----
    {
        int n4 = HQ * HQ / 4;
        split_kernel<<<(n4 + 255) / 256, 256, 0, st2>>>(wd, wdH, wdL, n4);
        cudaEventRecord(evWd, st2);
    }

    // ---- join: attention, then out-proj ----
    cudaStreamWaitEvent(0, evKV, 0);
    attn_mma_kernel<<<dim3(S_LEN / 64, NH, BDIM), 128, ATT_SMEM>>>(
        qsH, qsL, ksH, ksL, vtH, vtL, aoH, aoL);
    cudaStreamWaitEvent(0, evWd, 0);
    gemm3_kernel<<<dim3(HQ / GBN, MROWS / GBM), 256, GEMM_SMEM>>>(aoH, aoL, wdH, wdL, out, HQ, HQ);
}